// round 5
// baseline (speedup 1.0000x reference)
#include <cuda_runtime.h>

// out[b, :] = table_bits[idx(b), :],  idx(b) = sum_k idx_bits[b,k] << (5-k)
// table_bits: [64,64] f32 (16 KB), idx_bits: [262144,6] i32, out: [262144,64] f32.
//
// One wave: 512 blocks x 16 warps; warp owns 32 consecutive rows (8 KB output).
// Per warp: 6 coalesced LDG.32 (prefetched BEFORE the smem-table barrier),
// 6 ballots -> six 64-bit windows, then 16 x {LDS.128, contiguous STG.128}.

#define BATCH   262144
#define THREADS 512
#define WARPS   (THREADS / 32)                        // 16
#define ROWS_PER_WARP 32
#define GRID (BATCH / (ROWS_PER_WARP * WARPS))        // 512 blocks -> single wave

__global__ __launch_bounds__(THREADS)
void spike_lookup_kernel(const float4* __restrict__ table4,  // 64*16 float4
                         const int*    __restrict__ bits,    // BATCH*6
                         float4*       __restrict__ out4)    // BATCH*16
{
    __shared__ float4 t[64 * 16];     // 16 KB; row r at t[r*16 .. r*16+15]

    const int lane  = threadIdx.x & 31;
    const int gwarp = blockIdx.x * WARPS + (threadIdx.x >> 5);

    // ---- Prefetch this warp's 192 index ints (6 independent coalesced LDGs)
    //      BEFORE the table fill + barrier, so their latency overlaps it. ----
    const int* __restrict__ p = bits + gwarp * 192;
    int v0 = p[lane];
    int v1 = p[lane + 32];
    int v2 = p[lane + 64];
    int v3 = p[lane + 96];
    int v4 = p[lane + 128];
    int v5 = p[lane + 160];

    #pragma unroll
    for (int i = threadIdx.x; i < 64 * 16; i += THREADS)
        t[i] = table4[i];
    __syncthreads();

    unsigned c0 = __ballot_sync(0xFFFFFFFFu, v0 != 0);  // int m -> bit m
    unsigned c1 = __ballot_sync(0xFFFFFFFFu, v1 != 0);
    unsigned c2 = __ballot_sync(0xFFFFFFFFu, v2 != 0);
    unsigned c3 = __ballot_sync(0xFFFFFFFFu, v3 != 0);
    unsigned c4 = __ballot_sync(0xFFFFFFFFu, v4 != 0);
    unsigned c5 = __ballot_sync(0xFFFFFFFFu, v5 != 0);

    // 64-bit windows: U[k] covers bit offsets [32k, 32k+64)
    unsigned long long U0 = (unsigned long long)c0 | ((unsigned long long)c1 << 32);
    unsigned long long U1 = (unsigned long long)c1 | ((unsigned long long)c2 << 32);
    unsigned long long U2 = (unsigned long long)c2 | ((unsigned long long)c3 << 32);
    unsigned long long U3 = (unsigned long long)c3 | ((unsigned long long)c4 << 32);
    unsigned long long U4 = (unsigned long long)c4 | ((unsigned long long)c5 << 32);
    unsigned long long U5 = (unsigned long long)c5;   // offsets 160..186 fit alone

    const int j    = lane & 15;        // float4 column within the 64-float row
    const int half = lane >> 4;        // row parity within the pair

    float4* __restrict__ dst = out4 + (long long)gwarp * 512 + lane;

    #pragma unroll
    for (int i = 0; i < 16; i++) {
        int sh = 12 * i + 6 * half;    // bit offset of row r = 2i+half
        int w  = sh >> 5;              // per i, only 2 possible values -> SELs
        unsigned long long u =
            (w == 0) ? U0 : (w == 1) ? U1 : (w == 2) ? U2 :
            (w == 3) ? U3 : (w == 4) ? U4 : U5;
        unsigned vb = (unsigned)(u >> (sh & 31)) & 63u;
        int idx = (int)(__brev(vb) >> 26);     // k=0 is MSB (weight 32)

        dst[i * 32] = t[idx * 16 + j];         // contiguous 512B STG per warp
    }
}

extern "C" void kernel_launch(void* const* d_in, const int* in_sizes, int n_in,
                              void* d_out, int out_size)
{
    const float4* table4 = (const float4*)d_in[0];
    const int*    bits   = (const int*)d_in[1];
    float4*       out4   = (float4*)d_out;

    spike_lookup_kernel<<<GRID, THREADS>>>(table4, bits, out4);
}

// round 6
// speedup vs baseline: 1.0769x; 1.0769x over previous
#include <cuda_runtime.h>

// out[b, :] = table_bits[idx(b), :],  idx(b) = sum_k idx_bits[b,k] << (5-k)
// table_bits: [64,64] f32 (16 KB -> lives in L1), idx_bits: [262144,6] i32,
// out: [262144,64] f32 (64 MB).
//
// No smem, no barrier: warp owns 16 consecutive rows. 3 coalesced LDG.32 +
// 3 ballots gather 96 index bits; then 8 x {LDG.128 table row (L1 hit),
// contiguous STG.128}, loads batched 4-wide for MLP.

#define BATCH   262144
#define THREADS 256
#define ROWS_PER_WARP 16
#define GRID (BATCH / (ROWS_PER_WARP * (THREADS / 32)))   // 2048 blocks

__global__ __launch_bounds__(THREADS)
void spike_lookup_kernel(const float4* __restrict__ table4,  // 64*16 float4
                         const int*    __restrict__ bits,    // BATCH*6
                         float4*       __restrict__ out4)    // BATCH*16
{
    const int lane  = threadIdx.x & 31;
    const int gwarp = blockIdx.x * (THREADS / 32) + (threadIdx.x >> 5);

    // 16 rows * 6 ints = 96 ints, fully coalesced.
    const int* __restrict__ p = bits + gwarp * 96;
    unsigned b0 = __ballot_sync(0xFFFFFFFFu, p[lane]      != 0); // int m -> bit m
    unsigned b1 = __ballot_sync(0xFFFFFFFFu, p[lane + 32] != 0);
    unsigned b2 = __ballot_sync(0xFFFFFFFFu, p[lane + 64] != 0);

    unsigned long long u01 = (unsigned long long)b0 | ((unsigned long long)b1 << 32);
    unsigned long long u12 = (unsigned long long)b1 | ((unsigned long long)b2 << 32);

    const int j    = lane & 15;        // float4 column within the 64-float row
    const int half = lane >> 4;        // row parity within the pair

    float4* __restrict__ dst = out4 + (long long)gwarp * 256 + lane;

    #pragma unroll
    for (int g = 0; g < 2; g++) {
        float4 v[4];
        #pragma unroll
        for (int i = 0; i < 4; i++) {
            int r  = 2 * (g * 4 + i) + half;          // local row 0..15
            int sh = 6 * r;
            unsigned vb = (r < 10) ? (unsigned)(u01 >> sh)
                                   : (unsigned)(u12 >> (sh - 32));
            int idx = (int)(__brev(vb & 63u) >> 26);  // k=0 is MSB (weight 32)
            v[i] = __ldg(&table4[idx * 16 + j]);      // L1-resident table
        }
        #pragma unroll
        for (int i = 0; i < 4; i++)
            dst[(g * 4 + i) * 32] = v[i];             // contiguous 512B per warp
    }
}

extern "C" void kernel_launch(void* const* d_in, const int* in_sizes, int n_in,
                              void* d_out, int out_size)
{
    const float4* table4 = (const float4*)d_in[0];
    const int*    bits   = (const int*)d_in[1];
    float4*       out4   = (float4*)d_out;

    spike_lookup_kernel<<<GRID, THREADS>>>(table4, bits, out4);
}

// round 7
// speedup vs baseline: 1.0886x; 1.0108x over previous
#include <cuda_runtime.h>

// out[b, :] = table_bits[idx(b), :],  idx(b) = sum_k idx_bits[b,k] << (5-k)
// table values are 0.0/1.0 pulses -> pack each 64-float row into a 64-bit mask
// once (build kernel), then the main kernel expands masks with pure ALU.
// idx_bits: [262144,6] i32.  out: [262144,64] f32 (64 MB).

#define BATCH   262144
#define THREADS 256
#define ROWS_PER_WARP 16
#define GRID (BATCH / (ROWS_PER_WARP * (THREADS / 32)))   // 2048 blocks

// Mask m for table row r: column c (0..63) lives at bit (63 - c).
__device__ unsigned long long g_masks[64];

__global__ void build_masks_kernel(const float* __restrict__ table)
{
    int w    = (blockIdx.x * blockDim.x + threadIdx.x) >> 5;   // 0..63 table row
    int lane = threadIdx.x & 31;
    float v0 = table[w * 64 + lane];        // cols 0..31
    float v1 = table[w * 64 + 32 + lane];   // cols 32..63
    unsigned hi = __brev(__ballot_sync(0xFFFFFFFFu, v0 > 0.5f)); // col c -> bit 31-c
    unsigned lo = __brev(__ballot_sync(0xFFFFFFFFu, v1 > 0.5f));
    if (lane == 0)
        g_masks[w] = ((unsigned long long)hi << 32) | (unsigned long long)lo;
}

__device__ __forceinline__ float bit_to_1f(unsigned nib, int k)
{
    // k=0 -> bit3 (col 4j), ... k=3 -> bit0. 1.0f = 0x3F800000.
    return __int_as_float(((int)(nib << (28 + k)) >> 31) & 0x3F800000);
}

__global__ __launch_bounds__(THREADS)
void spike_lookup_kernel(const int* __restrict__ bits,    // BATCH*6
                         float4*    __restrict__ out4)    // BATCH*16
{
    const int lane  = threadIdx.x & 31;
    const int gwarp = blockIdx.x * (THREADS / 32) + (threadIdx.x >> 5);

    // 16 rows * 6 ints = 96 ints, fully coalesced.
    const int* __restrict__ p = bits + gwarp * 96;
    unsigned b0 = __ballot_sync(0xFFFFFFFFu, p[lane]      != 0); // int m -> bit m
    unsigned b1 = __ballot_sync(0xFFFFFFFFu, p[lane + 32] != 0);
    unsigned b2 = __ballot_sync(0xFFFFFFFFu, p[lane + 64] != 0);

    unsigned long long u01 = (unsigned long long)b0 | ((unsigned long long)b1 << 32);
    unsigned long long u12 = (unsigned long long)b1 | ((unsigned long long)b2 << 32);

    const int j    = lane & 15;        // float4 column within the 64-float row
    const int half = lane >> 4;        // row parity within the pair
    const int s    = 60 - 4 * j;       // shift: cols 4j..4j+3 -> nibble bits 3..0

    float4* __restrict__ dst = out4 + (long long)gwarp * 256 + lane;

    #pragma unroll
    for (int g = 0; g < 2; g++) {
        float4 v[4];
        #pragma unroll
        for (int i = 0; i < 4; i++) {
            int r  = 2 * (g * 4 + i) + half;          // local row 0..15
            int sh = 6 * r;
            unsigned vb = (r < 10) ? (unsigned)(u01 >> sh)
                                   : (unsigned)(u12 >> (sh - 32));
            int idx = (int)(__brev(vb & 63u) >> 26);  // k=0 is MSB (weight 32)

            unsigned long long m = __ldg(&g_masks[idx]);  // 4-line-hot broadcast
            unsigned nib = (unsigned)(m >> s) & 0xFu;

            v[i].x = bit_to_1f(nib, 0);
            v[i].y = bit_to_1f(nib, 1);
            v[i].z = bit_to_1f(nib, 2);
            v[i].w = bit_to_1f(nib, 3);
        }
        #pragma unroll
        for (int i = 0; i < 4; i++)
            dst[(g * 4 + i) * 32] = v[i];             // contiguous 512B per warp
    }
}

extern "C" void kernel_launch(void* const* d_in, const int* in_sizes, int n_in,
                              void* d_out, int out_size)
{
    const float* table = (const float*)d_in[0];
    const int*   bits  = (const int*)d_in[1];
    float4*      out4  = (float4*)d_out;

    build_masks_kernel<<<2, 1024>>>(table);           // 64 warps, one per row
    spike_lookup_kernel<<<GRID, THREADS>>>(bits, out4);
}